// round 15
// baseline (speedup 1.0000x reference)
#include <cuda_runtime.h>
#include <cuda_fp16.h>
#include <math.h>
#include <stdint.h>

// ---------------- problem constants ----------------
#define TB   2
#define TT   2048
#define TC   2048
#define HD   128
#define NH_Q 16      // R*KVH
#define NH_KV 8

// ---------------- device scratch (no allocs allowed) ----------------
__device__ __half g_Xh[(size_t)4096 * 2048];   // x fp16 single [m, k]
__device__ __half g_Oh[(size_t)4096 * 2048];   // attn out fp16 single [m, h*128+d]
// rope'd Q (split) / K (single) and V (single), head-major [BH][T][D]
__device__ __half g_Qh[(size_t)TB * NH_Q  * TT * HD];
__device__ __half g_Ql[(size_t)TB * NH_Q  * TT * HD];
__device__ __half g_Kh[(size_t)TB * NH_KV * TT * HD];
__device__ __half g_Vh[(size_t)TB * NH_KV * TT * HD];
// weights transposed to K-major [N, K=2048], single fp16
__device__ __half g_Wq[(size_t)2048 * 2048];
__device__ __half g_Wk[(size_t)1024 * 2048];
__device__ __half g_Wv[(size_t)1024 * 2048];
__device__ __half g_Wo[(size_t)2048 * 2048];
// rope sin/cos table [T][64]
__device__ float g_sinT[(size_t)TT * 64];
__device__ float g_cosT[(size_t)TT * 64];

// ---------------- PTX helpers ----------------
__device__ __forceinline__ uint32_t smem_u32(const void* p) {
    uint32_t a;
    asm("{ .reg .u64 t; cvta.to.shared.u64 t, %1; cvt.u32.u64 %0, t; }"
        : "=r"(a) : "l"(p));
    return a;
}
__device__ __forceinline__ void cp16(uint32_t s, const void* g) {
    asm volatile("cp.async.cg.shared.global [%0], [%1], 16;" :: "r"(s), "l"(g));
}
__device__ __forceinline__ void cp_commit() {
    asm volatile("cp.async.commit_group;" ::: "memory");
}
template<int N> __device__ __forceinline__ void cp_wait() {
    asm volatile("cp.async.wait_group %0;" :: "n"(N) : "memory");
}
__device__ __forceinline__ void ldsm4(uint32_t* d, uint32_t addr) {
    asm volatile("ldmatrix.sync.aligned.m8n8.x4.shared.b16 {%0,%1,%2,%3}, [%4];"
                 : "=r"(d[0]), "=r"(d[1]), "=r"(d[2]), "=r"(d[3]) : "r"(addr));
}
__device__ __forceinline__ void ldsm4t(uint32_t* d, uint32_t addr) {
    asm volatile("ldmatrix.sync.aligned.m8n8.x4.trans.shared.b16 {%0,%1,%2,%3}, [%4];"
                 : "=r"(d[0]), "=r"(d[1]), "=r"(d[2]), "=r"(d[3]) : "r"(addr));
}
__device__ __forceinline__ void mma16816h(float* c, const uint32_t* a,
                                          const uint32_t* b) {
    asm volatile(
        "mma.sync.aligned.m16n8k16.row.col.f32.f16.f16.f32 "
        "{%0,%1,%2,%3}, {%4,%5,%6,%7}, {%8,%9}, {%0,%1,%2,%3};"
        : "+f"(c[0]), "+f"(c[1]), "+f"(c[2]), "+f"(c[3])
        : "r"(a[0]), "r"(a[1]), "r"(a[2]), "r"(a[3]), "r"(b[0]), "r"(b[1]));
}
__device__ __forceinline__ void split2h(float a, float b, uint32_t& hi, uint32_t& lo) {
    __half2 h = __floats2half2_rn(a, b);
    float ra = a - __half2float(h.x);
    float rb = b - __half2float(h.y);
    __half2 l = __floats2half2_rn(ra, rb);
    hi = *reinterpret_cast<uint32_t*>(&h);
    lo = *reinterpret_cast<uint32_t*>(&l);
}
__device__ __forceinline__ uint32_t pack2h(float a, float b) {
    __half2 h = __floats2half2_rn(a, b);
    return *reinterpret_cast<uint32_t*>(&h);
}
// 50*tanh(x*CS) where CS = rsqrt(128)/50, via exp (accurate ~1e-6 rel)
__device__ __forceinline__ float softcap(float x) {
    const float C2 = 2.0f * 0.08838834764831845f / 50.0f;
    float t = __expf(x * C2);
    return 50.0f * __fdividef(t - 1.0f, t + 1.0f);
}

// ---------------- rope table ----------------
__global__ void rope_tab() {
    int gid = blockIdx.x * 256 + threadIdx.x;   // 0..131071
    int d = gid & 63, t = gid >> 6;
    double ts_d = pow(1.0e6, (double)d * (1.0 / 64.0));
    float arg = __fdiv_rn((float)t, (float)ts_d);
    double da = (double)arg;
    double n  = rint(da * 0.15915494309189535);
    double rr = fma(n, -6.283185307179586, da);
    float rf = (float)rr;
    g_sinT[gid] = sinf(rf);
    g_cosT[gid] = cosf(rf);
}

// ---------------- conversion kernels ----------------
__global__ void cvt_x(const float* __restrict__ x) {
    size_t i = (size_t)blockIdx.x * 256 + threadIdx.x;   // per float4
    float4 v = ((const float4*)x)[i];
    ((uint32_t*)g_Xh)[i * 2]     = pack2h(v.x, v.y);
    ((uint32_t*)g_Xh)[i * 2 + 1] = pack2h(v.z, v.w);
}

// all 4 weight transposes in one launch
__global__ void cvt_w_all(const float* __restrict__ q, const float* __restrict__ k,
                          const float* __restrict__ v, const float* __restrict__ o) {
    __shared__ float tile[32][33];
    int bx = blockIdx.x;
    const float* W; __half* WT; int N, nb;
    if (bx < 64)       { W = q; WT = g_Wq; N = 2048; nb = bx * 32; }
    else if (bx < 96)  { W = k; WT = g_Wk; N = 1024; nb = (bx - 64) * 32; }
    else if (bx < 128) { W = v; WT = g_Wv; N = 1024; nb = (bx - 96) * 32; }
    else               { W = o; WT = g_Wo; N = 2048; nb = (bx - 128) * 32; }
    int kb = blockIdx.y * 32;
    int tx = threadIdx.x & 31, ty = threadIdx.x >> 5;
#pragma unroll
    for (int r = 0; r < 32; r += 8)
        tile[ty + r][tx] = W[(size_t)(kb + ty + r) * N + nb + tx];
    __syncthreads();
#pragma unroll
    for (int r = 0; r < 32; r += 8) {
        int n = nb + ty + r, kk = kb + tx;
        WT[(size_t)n * 2048 + kk] = __float2half_rn(tile[tx][ty + r]);
    }
}

// ---------------- mma.sync fp16 GEMM: CTA 256x128, warp 64x32, BK=64 ---------
// 512 threads, 16 warps (4 wm x 4 wn).  SEL 0: fused QKV (N-space 4096 =
// [Q 2048 | K 1024 | V 1024]) with rope epilogue; SEL 1: out-proj -> d_out.
#define ROWB     144                    // 128 data bytes + 16 pad (conflict-free)
#define BOFFS    36864                  // B tile offset (A: 256 rows x 144)
#define STAGEB   55296                  // A(256x144) + B(128x144)
#define NSTG     3
#define SMEM_GEMM (NSTG * STAGEB)       // 165888

__device__ __forceinline__ void load_stage(uint32_t sb,
        const __half* __restrict__ Ah, const __half* __restrict__ Bp,
        int bm, int k0, int tid) {
#pragma unroll
    for (int j = 0; j < 6; j++) {
        int idx = tid + j * 512;            // 0..3071
        if (idx < 2048) {
            int r = idx >> 3, c = idx & 7;
            cp16(sb + (uint32_t)r * ROWB + (uint32_t)c * 16u,
                 Ah + (size_t)(bm + r) * 2048 + k0 + c * 8);
        } else {
            int i2 = idx - 2048;
            int r = i2 >> 3, c = i2 & 7;
            cp16(sb + BOFFS + (uint32_t)r * ROWB + (uint32_t)c * 16u,
                 Bp + (size_t)r * 2048 + k0 + c * 8);
        }
    }
}

template<int SEL>
__global__ void __launch_bounds__(512, 1) gemm_f16(float* __restrict__ outp) {
    extern __shared__ __align__(128) char dsm[];
    const uint32_t smem0 = smem_u32(dsm);

    const int tid = threadIdx.x;
    const int lid = tid & 31;
    const int wid = tid >> 5;
    const int wm = wid >> 2;            // 0..3  (64-row slab within 256)
    const int wn = wid & 3;             // 0..3  (32-col slab within 128)
    const int bn = blockIdx.x * 128;
    const int bm = blockIdx.y * 256;

    const __half *Ah, *Bp;
    if (SEL == 1) {
        Ah = g_Oh;
        Bp = g_Wo + (size_t)bn * 2048;
    } else {
        Ah = g_Xh;
        if (bn < 2048)      Bp = g_Wq + (size_t)bn * 2048;
        else if (bn < 3072) Bp = g_Wk + (size_t)(bn - 2048) * 2048;
        else                Bp = g_Wv + (size_t)(bn - 3072) * 2048;
    }

    // A-fragment lane addressing (m16k16 via ldsm4)
    const int r8 = lid & 7, gq = lid >> 3;
    const uint32_t aoff = (uint32_t)((gq & 1) * 8 + r8) * ROWB +
                          (uint32_t)(gq >> 1) * 16u + (uint32_t)wm * 64u * ROWB;
    // B-fragment lane addressing (paired ldsm4: two n8 tiles per load)
    const uint32_t boff = BOFFS + (uint32_t)((lid >> 4) * 8 + (lid & 7)) * ROWB +
                          (uint32_t)((lid >> 3) & 1) * 16u + (uint32_t)wn * 32u * ROWB;

    float acc[4][4][4];
#pragma unroll
    for (int i = 0; i < 4; i++)
#pragma unroll
        for (int j = 0; j < 4; j++)
#pragma unroll
            for (int k = 0; k < 4; k++) acc[i][j][k] = 0.f;

    load_stage(smem0, Ah, Bp, bm, 0, tid);
    cp_commit();
    load_stage(smem0 + STAGEB, Ah, Bp, bm, 64, tid);
    cp_commit();

    const int NI = 32;                  // 2048 / 64
    int sidx = 0;
    for (int i = 0; i < NI; i++) {
        cp_wait<1>();
        __syncthreads();
        if (i + 2 < NI) {
            int ns = sidx + 2; if (ns >= NSTG) ns -= NSTG;
            load_stage(smem0 + ns * STAGEB, Ah, Bp, bm, (i + 2) * 64, tid);
        }
        cp_commit();                    // one group per iter (may be empty)

        const uint32_t sb = smem0 + sidx * STAGEB;
#pragma unroll
        for (int kp = 0; kp < 4; kp++) {
            uint32_t af[4][4], bf[2][4];
#pragma unroll
            for (int mt = 0; mt < 4; mt++)
                ldsm4(af[mt], sb + aoff + mt * (16 * ROWB) + kp * 32);
#pragma unroll
            for (int p = 0; p < 2; p++)
                ldsm4(bf[p], sb + boff + p * (16 * ROWB) + kp * 32);
#pragma unroll
            for (int mt = 0; mt < 4; mt++)
#pragma unroll
                for (int nt = 0; nt < 4; nt++)
                    mma16816h(acc[mt][nt], af[mt], &bf[nt >> 1][(nt & 1) * 2]);
        }
        if (++sidx >= NSTG) sidx = 0;
    }
    __syncthreads();                    // protect smem reuse by rope epilogue

    const int t4 = lid >> 2, t2 = (lid & 3) << 1;

    if (SEL == 0 && bn < 3072) {
        // ---- Q/K: stage fp32 tile (256x130) in smem, apply rope, emit fp16 --
        float* sQ = reinterpret_cast<float*>(dsm);   // [256][130] = 133120 B
#pragma unroll
        for (int mt = 0; mt < 4; mt++) {
            int r0 = wm * 64 + mt * 16 + t4;
#pragma unroll
            for (int half = 0; half < 2; half++) {
                int r = r0 + half * 8;
#pragma unroll
                for (int nt = 0; nt < 4; nt++) {
                    int col = wn * 32 + nt * 8 + t2;
                    sQ[r * 130 + col]     = acc[mt][nt][half * 2];
                    sQ[r * 130 + col + 1] = acc[mt][nt][half * 2 + 1];
                }
            }
        }
        __syncthreads();

        const bool isQ = (bn < 2048);
        const int head = isQ ? (bn >> 7) : ((bn - 2048) >> 7);
#pragma unroll
        for (int pass = 0; pass < 16; pass++) {
            int u = tid + pass * 512;          // 0..8191
            int r = u >> 5;                    // 0..255
            int d2 = (u & 31) * 2;             // 0,2,..,62
            int m = bm + r;
            int b = m >> 11, t = m & 2047;
            float u1a = sQ[r * 130 + d2],      u1b = sQ[r * 130 + d2 + 1];
            float u2a = sQ[r * 130 + d2 + 64], u2b = sQ[r * 130 + d2 + 65];
            float ca = g_cosT[t * 64 + d2],     sa_ = g_sinT[t * 64 + d2];
            float cb = g_cosT[t * 64 + d2 + 1], sb_ = g_sinT[t * 64 + d2 + 1];
            float y1a = u1a * ca - u2a * sa_, y1b = u1b * cb - u2b * sb_;
            float y2a = u2a * ca + u1a * sa_, y2b = u2b * cb + u1b * sb_;
            if (isQ) {
                size_t o = (((size_t)b * NH_Q + head) * TT + t) * HD + d2;
                uint32_t hi, lo;
                split2h(y1a, y1b, hi, lo);
                *(uint32_t*)(g_Qh + o) = hi;  *(uint32_t*)(g_Ql + o) = lo;
                split2h(y2a, y2b, hi, lo);
                *(uint32_t*)(g_Qh + o + 64) = hi;  *(uint32_t*)(g_Ql + o + 64) = lo;
            } else {
                size_t o = (((size_t)b * NH_KV + head) * TT + t) * HD + d2;
                *(uint32_t*)(g_Kh + o)      = pack2h(y1a, y1b);
                *(uint32_t*)(g_Kh + o + 64) = pack2h(y2a, y2b);
            }
        }
        return;
    }

    // ---- V (fp16 single) or out-proj (fp32) ----
#pragma unroll
    for (int mt = 0; mt < 4; mt++) {
        int m0 = bm + wm * 64 + mt * 16 + t4;
#pragma unroll
        for (int half = 0; half < 2; half++) {
            int m = m0 + half * 8;
            int b = m >> 11, t = m & 2047;
            if (SEL == 1) {
                float* dst = outp + (size_t)m * 2048 + bn;
#pragma unroll
                for (int nt = 0; nt < 4; nt++) {
                    int col = wn * 32 + nt * 8 + t2;
                    *(float2*)(dst + col) =
                        make_float2(acc[mt][nt][half * 2], acc[mt][nt][half * 2 + 1]);
                }
            } else {
                int head = (bn - 3072) >> 7;
                size_t ro = (((size_t)b * NH_KV + head) * TT + t) * HD;
#pragma unroll
                for (int nt = 0; nt < 4; nt++) {
                    int col = wn * 32 + nt * 8 + t2;
                    *(uint32_t*)(g_Vh + ro + col) =
                        pack2h(acc[mt][nt][half * 2], acc[mt][nt][half * 2 + 1]);
                }
            }
        }
    }
}

// =====================================================================
// Flash attention: BM=64, BN=64, 4 warps / 128 threads, 2 CTAs/SM.
// Q split fp16 (2-term), K/V single fp16, P single fp16.  fp32 accum.
// =====================================================================
#define ARSB  272
#define QSZ   (64 * ARSB)        // 17408 per Q array
#define KVARR (64 * ARSB)        // 17408 per operand array
#define KVSTG (2 * KVARR)        // 34816 per stage (Kh, Vh)
#define SMEM_ATTN (2 * QSZ + 2 * KVSTG)   // 104448

__device__ __forceinline__ void load_kv(uint32_t sb,
        const __half* __restrict__ Khp, const __half* __restrict__ Vhp,
        int kv0, int tid) {
#pragma unroll
    for (int tpass = 0; tpass < 8; tpass++) {
        int idx = tid + tpass * 128;        // 0..1023
        int r = idx >> 4, cc = idx & 15;
        uint32_t so = (uint32_t)r * ARSB + (uint32_t)cc * 16u;
        size_t go = (size_t)(kv0 + r) * HD + cc * 8;
        cp16(sb +         so, Khp + go);
        cp16(sb + KVARR + so, Vhp + go);
    }
}

__global__ void __launch_bounds__(128) attn_mma() {
    extern __shared__ __align__(128) char asmem[];
    const uint32_t s0  = smem_u32(asmem);
    const uint32_t qhS = s0;
    const uint32_t qlS = s0 + QSZ;
    const uint32_t kvb = s0 + 2 * QSZ;

    const int i0 = gridDim.x - 1 - blockIdx.x;    // heavy blocks first
    const int bh = blockIdx.y;                    // b*16 + h
    const int b  = bh >> 4;
    const int h  = bh & 15;
    const int hkv = h & 7;

    const __half* Qhp = g_Qh + (size_t)bh * TT * HD;
    const __half* Qlp = g_Ql + (size_t)bh * TT * HD;
    const size_t kvo = ((size_t)b * NH_KV + hkv) * TT * HD;
    const __half* Khp = g_Kh + kvo;
    const __half* Vhp = g_Vh + kvo;

    const int tid = threadIdx.x, lid = tid & 31, wid = tid >> 5;
    const int t4 = lid >> 2, t2g = lid & 3;
    const int warpRow = wid * 16;

    const uint32_t a_off = (uint32_t)(warpRow + (lid & 7) + ((lid >> 3) & 1) * 8) * ARSB +
                           (uint32_t)(lid >> 4) * 16u;
    const uint32_t bk_off = (uint32_t)(lid & 7) * ARSB + (uint32_t)(lid >> 3) * 16u;
    const uint32_t v_off  = (uint32_t)((lid & 7) + ((lid >> 3) & 1) * 8) * ARSB +
                            (uint32_t)(lid >> 4) * 16u;

    // load Q tile (hi+lo): 64 rows x 16 chunks
    {
        int r0q = i0 * 64;
#pragma unroll
        for (int tp = 0; tp < 8; tp++) {
            int idx = tid + tp * 128;       // 0..1023
            int r = idx >> 4, cc = idx & 15;
            uint32_t so = (uint32_t)r * ARSB + (uint32_t)cc * 16u;
            size_t go = (size_t)(r0q + r) * HD + cc * 8;
            cp16(qhS + so, Qhp + go);
            cp16(qlS + so, Qlp + go);
        }
    }
    load_kv(kvb, Khp, Vhp, 0, tid);
    cp_commit();

    float oacc[16][4];
#pragma unroll
    for (int i = 0; i < 16; i++)
#pragma unroll
        for (int j = 0; j < 4; j++) oacc[i][j] = 0.f;
    float mA = -1e30f, mB = -1e30f, lA = 0.f, lB = 0.f;

    const int rowA = i0 * 64 + warpRow + t4;
    const int rowB = rowA + 8;
    const int nj = i0 + 1;

    for (int j = 0; j < nj; j++) {
        if (j + 1 < nj) {
            load_kv(kvb + ((j + 1) & 1) * KVSTG, Khp, Vhp, (j + 1) * 64, tid);
            cp_commit();
            cp_wait<1>();
        } else {
            cp_wait<0>();
        }
        __syncthreads();

        const uint32_t sb = kvb + (j & 1) * KVSTG;

        // ---- S = Q K^T (Q 2-term, K single) ----
        float sa[8][4];
#pragma unroll
        for (int nt = 0; nt < 8; nt++)
#pragma unroll
            for (int q = 0; q < 4; q++) sa[nt][q] = 0.f;

#pragma unroll
        for (int kp = 0; kp < 4; kp++) {
            uint32_t q0h[4], q1h[4], q0l[4], q1l[4];
            ldsm4(q0h, qhS + a_off + kp * 64);
            ldsm4(q1h, qhS + a_off + kp * 64 + 32);
            ldsm4(q0l, qlS + a_off + kp * 64);
            ldsm4(q1l, qlS + a_off + kp * 64 + 32);
#pragma unroll
            for (int nt = 0; nt < 8; nt++) {
                uint32_t kh[4];
                ldsm4(kh, sb + bk_off + nt * (8 * ARSB) + kp * 64);
                mma16816h(sa[nt], q0h, kh);
                mma16816h(sa[nt], q0l, kh);
                mma16816h(sa[nt], q1h, kh + 2);
                mma16816h(sa[nt], q1l, kh + 2);
            }
        }

        // ---- softcap + mask + online softmax ----
        float mxA = -1e30f, mxB = -1e30f;
#pragma unroll
        for (int nt = 0; nt < 8; nt++) {
            int c0 = j * 64 + nt * 8 + 2 * t2g;
            float v0 = softcap(sa[nt][0]);
            float v1 = softcap(sa[nt][1]);
            float v2 = softcap(sa[nt][2]);
            float v3 = softcap(sa[nt][3]);
            if (c0     > rowA) v0 = -1e30f;
            if (c0 + 1 > rowA) v1 = -1e30f;
            if (c0     > rowB) v2 = -1e30f;
            if (c0 + 1 > rowB) v3 = -1e30f;
            sa[nt][0] = v0; sa[nt][1] = v1; sa[nt][2] = v2; sa[nt][3] = v3;
            mxA = fmaxf(mxA, fmaxf(v0, v1));
            mxB = fmaxf(mxB, fmaxf(v2, v3));
        }
        mxA = fmaxf(mxA, __shfl_xor_sync(0xffffffffu, mxA, 1));
        mxA = fmaxf(mxA, __shfl_xor_sync(0xffffffffu, mxA, 2));
        mxB = fmaxf(mxB, __shfl_xor_sync(0xffffffffu, mxB, 1));
        mxB = fmaxf(mxB, __shfl_xor_sync(0xffffffffu, mxB, 2));

        float mAn = fmaxf(mA, mxA), mBn = fmaxf(mB, mxB);
        float fA = __expf(mA - mAn), fB = __expf(mB - mBn);
        mA = mAn; mB = mBn;

        float sA = 0.f, sB = 0.f;
#pragma unroll
        for (int nt = 0; nt < 8; nt++) {
            float p0 = __expf(sa[nt][0] - mA);
            float p1 = __expf(sa[nt][1] - mA);
            float p2 = __expf(sa[nt][2] - mB);
            float p3 = __expf(sa[nt][3] - mB);
            sa[nt][0] = p0; sa[nt][1] = p1; sa[nt][2] = p2; sa[nt][3] = p3;
            sA += p0 + p1; sB += p2 + p3;
        }
        sA += __shfl_xor_sync(0xffffffffu, sA, 1);
        sA += __shfl_xor_sync(0xffffffffu, sA, 2);
        sB += __shfl_xor_sync(0xffffffffu, sB, 1);
        sB += __shfl_xor_sync(0xffffffffu, sB, 2);
        lA = lA * fA + sA;
        lB = lB * fB + sB;
#pragma unroll
        for (int nt = 0; nt < 16; nt++) {
            oacc[nt][0] *= fA; oacc[nt][1] *= fA;
            oacc[nt][2] *= fB; oacc[nt][3] *= fB;
        }

        // ---- O += P V (P single fp16 from registers, V single) ----
#pragma unroll
        for (int ks = 0; ks < 4; ks++) {
            uint32_t pah[4];
            pah[0] = pack2h(sa[2 * ks][0],     sa[2 * ks][1]);
            pah[1] = pack2h(sa[2 * ks][2],     sa[2 * ks][3]);
            pah[2] = pack2h(sa[2 * ks + 1][0], sa[2 * ks + 1][1]);
            pah[3] = pack2h(sa[2 * ks + 1][2], sa[2 * ks + 1][3]);
#pragma unroll
            for (int ntp = 0; ntp < 8; ntp++) {
                uint32_t vh[4];
                ldsm4t(vh, sb + KVARR + v_off + ks * (16 * ARSB) + ntp * 32);
                mma16816h(oacc[2 * ntp],     pah, vh);
                mma16816h(oacc[2 * ntp + 1], pah, vh + 2);
            }
        }
        __syncthreads();
    }

    // ---- epilogue: normalize, write g_Oh (fp16 single) [m][h*128+d] ----
    float invA = 1.f / lA, invB = 1.f / lB;
    size_t mAr = (size_t)b * 2048 + (size_t)rowA;   // rowA is global t
    size_t mBr = mAr + 8;
    int colbase = h * 128 + 2 * t2g;
#pragma unroll
    for (int nt = 0; nt < 16; nt++) {
        int c = colbase + nt * 8;
        *(uint32_t*)(g_Oh + mAr * 2048 + c) =
            pack2h(oacc[nt][0] * invA, oacc[nt][1] * invA);
        *(uint32_t*)(g_Oh + mBr * 2048 + c) =
            pack2h(oacc[nt][2] * invB, oacc[nt][3] * invB);
    }
}

// =====================================================================
// host entry
// =====================================================================
extern "C" void kernel_launch(void* const* d_in, const int* in_sizes, int n_in,
                              void* d_out, int out_size) {
    const float* x  = (const float*)d_in[0];
    // d_in[1] = mask (deterministic causal tril -> ignored)
    const float* qk = (const float*)d_in[2];
    const float* kk = (const float*)d_in[3];
    const float* vk = (const float*)d_in[4];
    const float* ok = (const float*)d_in[5];
    float* out = (float*)d_out;

    cudaFuncSetAttribute(gemm_f16<0>, cudaFuncAttributeMaxDynamicSharedMemorySize, SMEM_GEMM);
    cudaFuncSetAttribute(gemm_f16<1>, cudaFuncAttributeMaxDynamicSharedMemorySize, SMEM_GEMM);
    cudaFuncSetAttribute(attn_mma, cudaFuncAttributeMaxDynamicSharedMemorySize, SMEM_ATTN);

    // rope table + input conversion
    rope_tab<<<512, 256>>>();
    cvt_x<<<8192, 256>>>(x);
    cvt_w_all<<<dim3(192, 64), 256>>>(qk, kk, vk, ok);

    // fused QKV projection + rope epilogue (CTA 256x128, 512 thr, BK=64)
    gemm_f16<0><<<dim3(32, 16), 512, SMEM_GEMM>>>(nullptr);

    // tensor-core flash attention (writes g_Oh fp16 single)
    attn_mma<<<dim3(TT / 64, TB * NH_Q), 128, SMEM_ATTN>>>();

    // output projection
    gemm_f16<1><<<dim3(16, 16), 512, SMEM_GEMM>>>(out);
}

// round 16
// speedup vs baseline: 1.1096x; 1.1096x over previous
#include <cuda_runtime.h>
#include <cuda_fp16.h>
#include <math.h>
#include <stdint.h>

// ---------------- problem constants ----------------
#define TB   2
#define TT   2048
#define TC   2048
#define HD   128
#define NH_Q 16      // R*KVH
#define NH_KV 8

// ---------------- device scratch (no allocs allowed) ----------------
__device__ __half g_Xh[(size_t)4096 * 2048];   // x fp16 single [m, k]
__device__ __half g_Oh[(size_t)4096 * 2048];   // attn out fp16 single [m, h*128+d]
// rope'd Q (split) / K (single) and V (single), head-major [BH][T][D]
__device__ __half g_Qh[(size_t)TB * NH_Q  * TT * HD];
__device__ __half g_Ql[(size_t)TB * NH_Q  * TT * HD];
__device__ __half g_Kh[(size_t)TB * NH_KV * TT * HD];
__device__ __half g_Vh[(size_t)TB * NH_KV * TT * HD];
// weights transposed to K-major [N, K=2048], single fp16
__device__ __half g_Wq[(size_t)2048 * 2048];
__device__ __half g_Wk[(size_t)1024 * 2048];
__device__ __half g_Wv[(size_t)1024 * 2048];
__device__ __half g_Wo[(size_t)2048 * 2048];
// rope sin/cos table [T][64]
__device__ float g_sinT[(size_t)TT * 64];
__device__ float g_cosT[(size_t)TT * 64];

// ---------------- PTX helpers ----------------
__device__ __forceinline__ uint32_t smem_u32(const void* p) {
    uint32_t a;
    asm("{ .reg .u64 t; cvta.to.shared.u64 t, %1; cvt.u32.u64 %0, t; }"
        : "=r"(a) : "l"(p));
    return a;
}
__device__ __forceinline__ void cp16(uint32_t s, const void* g) {
    asm volatile("cp.async.cg.shared.global [%0], [%1], 16;" :: "r"(s), "l"(g));
}
__device__ __forceinline__ void cp_commit() {
    asm volatile("cp.async.commit_group;" ::: "memory");
}
template<int N> __device__ __forceinline__ void cp_wait() {
    asm volatile("cp.async.wait_group %0;" :: "n"(N) : "memory");
}
__device__ __forceinline__ void ldsm4(uint32_t* d, uint32_t addr) {
    asm volatile("ldmatrix.sync.aligned.m8n8.x4.shared.b16 {%0,%1,%2,%3}, [%4];"
                 : "=r"(d[0]), "=r"(d[1]), "=r"(d[2]), "=r"(d[3]) : "r"(addr));
}
__device__ __forceinline__ void ldsm4t(uint32_t* d, uint32_t addr) {
    asm volatile("ldmatrix.sync.aligned.m8n8.x4.trans.shared.b16 {%0,%1,%2,%3}, [%4];"
                 : "=r"(d[0]), "=r"(d[1]), "=r"(d[2]), "=r"(d[3]) : "r"(addr));
}
__device__ __forceinline__ void mma16816h(float* c, const uint32_t* a,
                                          const uint32_t* b) {
    asm volatile(
        "mma.sync.aligned.m16n8k16.row.col.f32.f16.f16.f32 "
        "{%0,%1,%2,%3}, {%4,%5,%6,%7}, {%8,%9}, {%0,%1,%2,%3};"
        : "+f"(c[0]), "+f"(c[1]), "+f"(c[2]), "+f"(c[3])
        : "r"(a[0]), "r"(a[1]), "r"(a[2]), "r"(a[3]), "r"(b[0]), "r"(b[1]));
}
__device__ __forceinline__ void split2h(float a, float b, uint32_t& hi, uint32_t& lo) {
    __half2 h = __floats2half2_rn(a, b);
    float ra = a - __half2float(h.x);
    float rb = b - __half2float(h.y);
    __half2 l = __floats2half2_rn(ra, rb);
    hi = *reinterpret_cast<uint32_t*>(&h);
    lo = *reinterpret_cast<uint32_t*>(&l);
}
__device__ __forceinline__ uint32_t pack2h(float a, float b) {
    __half2 h = __floats2half2_rn(a, b);
    return *reinterpret_cast<uint32_t*>(&h);
}
// 50*tanh(x*CS) where CS = rsqrt(128)/50, via exp (accurate ~1e-6 rel)
__device__ __forceinline__ float softcap(float x) {
    const float C2 = 2.0f * 0.08838834764831845f / 50.0f;
    float t = __expf(x * C2);
    return 50.0f * __fdividef(t - 1.0f, t + 1.0f);
}

// ---------------- rope table ----------------
__global__ void rope_tab() {
    int gid = blockIdx.x * 256 + threadIdx.x;   // 0..131071
    int d = gid & 63, t = gid >> 6;
    double ts_d = pow(1.0e6, (double)d * (1.0 / 64.0));
    float arg = __fdiv_rn((float)t, (float)ts_d);
    double da = (double)arg;
    double n  = rint(da * 0.15915494309189535);
    double rr = fma(n, -6.283185307179586, da);
    float rf = (float)rr;
    g_sinT[gid] = sinf(rf);
    g_cosT[gid] = cosf(rf);
}

// ---------------- conversion kernels ----------------
__global__ void cvt_x(const float* __restrict__ x) {
    size_t i = (size_t)blockIdx.x * 256 + threadIdx.x;   // per float4
    float4 v = ((const float4*)x)[i];
    ((uint32_t*)g_Xh)[i * 2]     = pack2h(v.x, v.y);
    ((uint32_t*)g_Xh)[i * 2 + 1] = pack2h(v.z, v.w);
}

// all 4 weight transposes in one launch
__global__ void cvt_w_all(const float* __restrict__ q, const float* __restrict__ k,
                          const float* __restrict__ v, const float* __restrict__ o) {
    __shared__ float tile[32][33];
    int bx = blockIdx.x;
    const float* W; __half* WT; int N, nb;
    if (bx < 64)       { W = q; WT = g_Wq; N = 2048; nb = bx * 32; }
    else if (bx < 96)  { W = k; WT = g_Wk; N = 1024; nb = (bx - 64) * 32; }
    else if (bx < 128) { W = v; WT = g_Wv; N = 1024; nb = (bx - 96) * 32; }
    else               { W = o; WT = g_Wo; N = 2048; nb = (bx - 128) * 32; }
    int kb = blockIdx.y * 32;
    int tx = threadIdx.x & 31, ty = threadIdx.x >> 5;
#pragma unroll
    for (int r = 0; r < 32; r += 8)
        tile[ty + r][tx] = W[(size_t)(kb + ty + r) * N + nb + tx];
    __syncthreads();
#pragma unroll
    for (int r = 0; r < 32; r += 8) {
        int n = nb + ty + r, kk = kb + tx;
        WT[(size_t)n * 2048 + kk] = __float2half_rn(tile[tx][ty + r]);
    }
}

// ---------------- mma.sync fp16 GEMM: CTA 128x128, warp 64x32, BK=64 ---------
// SEL 0: fused QKV projection, N-space 4096 = [Q 2048 | K 1024 | V 1024];
//        Q/K rope applied in-epilogue via smem staging + table.
// SEL 1: output projection (N=2048), writes d_out fp32.
#define ROWB     144                    // 128 data bytes + 16 pad (conflict-free)
#define BOFFS    18432                  // B tile offset (A: 128 rows x 144)
#define STAGEB   36864                  // A + B
#define NSTG     3
#define SMEM_GEMM (NSTG * STAGEB)       // 110592

__device__ __forceinline__ void load_stage(uint32_t sb,
        const __half* __restrict__ Ah, const __half* __restrict__ Bp,
        int bm, int k0, int tid) {
#pragma unroll
    for (int j = 0; j < 8; j++) {
        int idx = tid + j * 256;            // 0..2047
        if (idx < 1024) {
            int r = idx >> 3, c = idx & 7;
            cp16(sb + (uint32_t)r * ROWB + (uint32_t)c * 16u,
                 Ah + (size_t)(bm + r) * 2048 + k0 + c * 8);
        } else {
            int i2 = idx - 1024;
            int r = i2 >> 3, c = i2 & 7;
            cp16(sb + BOFFS + (uint32_t)r * ROWB + (uint32_t)c * 16u,
                 Bp + (size_t)r * 2048 + k0 + c * 8);
        }
    }
}

template<int SEL>
__global__ void __launch_bounds__(256, 2) gemm_f16(float* __restrict__ outp) {
    extern __shared__ __align__(128) char dsm[];
    const uint32_t smem0 = smem_u32(dsm);

    const int tid = threadIdx.x;
    const int lid = tid & 31;
    const int wid = tid >> 5;
    const int wm = wid >> 2;            // 0..1
    const int wn = wid & 3;             // 0..3
    const int bn = blockIdx.x * 128;
    const int bm = blockIdx.y * 128;

    const __half *Ah, *Bp;
    if (SEL == 1) {
        Ah = g_Oh;
        Bp = g_Wo + (size_t)bn * 2048;
    } else {
        Ah = g_Xh;
        if (bn < 2048)      Bp = g_Wq + (size_t)bn * 2048;
        else if (bn < 3072) Bp = g_Wk + (size_t)(bn - 2048) * 2048;
        else                Bp = g_Wv + (size_t)(bn - 3072) * 2048;
    }

    // A-fragment lane addressing (m16k16 via ldsm4)
    const int r8 = lid & 7, gq = lid >> 3;
    const uint32_t aoff = (uint32_t)((gq & 1) * 8 + r8) * ROWB +
                          (uint32_t)(gq >> 1) * 16u + (uint32_t)wm * 64u * ROWB;
    // B-fragment lane addressing (paired ldsm4: two n8 tiles per load)
    const uint32_t boff = BOFFS + (uint32_t)((lid >> 4) * 8 + (lid & 7)) * ROWB +
                          (uint32_t)((lid >> 3) & 1) * 16u + (uint32_t)wn * 32u * ROWB;

    float acc[4][4][4];
#pragma unroll
    for (int i = 0; i < 4; i++)
#pragma unroll
        for (int j = 0; j < 4; j++)
#pragma unroll
            for (int k = 0; k < 4; k++) acc[i][j][k] = 0.f;

    load_stage(smem0, Ah, Bp, bm, 0, tid);
    cp_commit();
    load_stage(smem0 + STAGEB, Ah, Bp, bm, 64, tid);
    cp_commit();

    const int NI = 32;                  // 2048 / 64
    int sidx = 0;
    for (int i = 0; i < NI; i++) {
        cp_wait<1>();
        __syncthreads();

        const uint32_t sb = smem0 + sidx * STAGEB;
#pragma unroll
        for (int kp = 0; kp < 4; kp++) {
            uint32_t af[4][4], bf[2][4];
#pragma unroll
            for (int mt = 0; mt < 4; mt++)
                ldsm4(af[mt], sb + aoff + mt * (16 * ROWB) + kp * 32);
#pragma unroll
            for (int p = 0; p < 2; p++)
                ldsm4(bf[p], sb + boff + p * (16 * ROWB) + kp * 32);
#pragma unroll
            for (int mt = 0; mt < 4; mt++)
#pragma unroll
                for (int nt = 0; nt < 4; nt++)
                    mma16816h(acc[mt][nt], af[mt], &bf[nt >> 1][(nt & 1) * 2]);
            // issue next-stage loads after the first k-step: barrier releases
            // straight into MMAs, LDGSTS issue overlaps the tensor pipe
            if (kp == 0) {
                if (i + 2 < NI) {
                    int ns = sidx + 2; if (ns >= NSTG) ns -= NSTG;
                    load_stage(smem0 + ns * STAGEB, Ah, Bp, bm, (i + 2) * 64, tid);
                }
                cp_commit();            // exactly one group per iteration
            }
        }
        if (++sidx >= NSTG) sidx = 0;
    }
    __syncthreads();                    // protect smem reuse by rope epilogue

    const int t4 = lid >> 2, t2 = (lid & 3) << 1;

    if (SEL == 0 && bn < 3072) {
        // ---- Q/K: stage fp32 tile in smem, apply rope, emit fp16 ----
        float* sQ = reinterpret_cast<float*>(dsm);   // [128][130]
#pragma unroll
        for (int mt = 0; mt < 4; mt++) {
            int r0 = wm * 64 + mt * 16 + t4;
#pragma unroll
            for (int half = 0; half < 2; half++) {
                int r = r0 + half * 8;
#pragma unroll
                for (int nt = 0; nt < 4; nt++) {
                    int col = wn * 32 + nt * 8 + t2;
                    sQ[r * 130 + col]     = acc[mt][nt][half * 2];
                    sQ[r * 130 + col + 1] = acc[mt][nt][half * 2 + 1];
                }
            }
        }
        __syncthreads();

        const bool isQ = (bn < 2048);
        const int head = isQ ? (bn >> 7) : ((bn - 2048) >> 7);
#pragma unroll
        for (int pass = 0; pass < 16; pass++) {
            int u = tid + pass * 256;          // 0..4095
            int r = u >> 5;                    // 0..127
            int d2 = (u & 31) * 2;             // 0,2,..,62
            int m = bm + r;
            int b = m >> 11, t = m & 2047;
            float u1a = sQ[r * 130 + d2],      u1b = sQ[r * 130 + d2 + 1];
            float u2a = sQ[r * 130 + d2 + 64], u2b = sQ[r * 130 + d2 + 65];
            float ca = g_cosT[t * 64 + d2],     sa_ = g_sinT[t * 64 + d2];
            float cb = g_cosT[t * 64 + d2 + 1], sb_ = g_sinT[t * 64 + d2 + 1];
            float y1a = u1a * ca - u2a * sa_, y1b = u1b * cb - u2b * sb_;
            float y2a = u2a * ca + u1a * sa_, y2b = u2b * cb + u1b * sb_;
            if (isQ) {
                size_t o = (((size_t)b * NH_Q + head) * TT + t) * HD + d2;
                uint32_t hi, lo;
                split2h(y1a, y1b, hi, lo);
                *(uint32_t*)(g_Qh + o) = hi;  *(uint32_t*)(g_Ql + o) = lo;
                split2h(y2a, y2b, hi, lo);
                *(uint32_t*)(g_Qh + o + 64) = hi;  *(uint32_t*)(g_Ql + o + 64) = lo;
            } else {
                size_t o = (((size_t)b * NH_KV + head) * TT + t) * HD + d2;
                *(uint32_t*)(g_Kh + o)      = pack2h(y1a, y1b);
                *(uint32_t*)(g_Kh + o + 64) = pack2h(y2a, y2b);
            }
        }
        return;
    }

    // ---- V (fp16 single) or out-proj (fp32) ----
#pragma unroll
    for (int mt = 0; mt < 4; mt++) {
        int m0 = bm + wm * 64 + mt * 16 + t4;
#pragma unroll
        for (int half = 0; half < 2; half++) {
            int m = m0 + half * 8;
            int b = m >> 11, t = m & 2047;
            if (SEL == 1) {
                float* dst = outp + (size_t)m * 2048 + bn;
#pragma unroll
                for (int nt = 0; nt < 4; nt++) {
                    int col = wn * 32 + nt * 8 + t2;
                    *(float2*)(dst + col) =
                        make_float2(acc[mt][nt][half * 2], acc[mt][nt][half * 2 + 1]);
                }
            } else {
                int head = (bn - 3072) >> 7;
                size_t ro = (((size_t)b * NH_KV + head) * TT + t) * HD;
#pragma unroll
                for (int nt = 0; nt < 4; nt++) {
                    int col = wn * 32 + nt * 8 + t2;
                    *(uint32_t*)(g_Vh + ro + col) =
                        pack2h(acc[mt][nt][half * 2], acc[mt][nt][half * 2 + 1]);
                }
            }
        }
    }
}

// =====================================================================
// Flash attention: BM=64, BN=64, 4 warps / 128 threads, 2 CTAs/SM.
// Q split fp16 (2-term), K/V single fp16, P single fp16.  fp32 accum.
// =====================================================================
#define ARSB  272
#define QSZ   (64 * ARSB)        // 17408 per Q array
#define KVARR (64 * ARSB)        // 17408 per operand array
#define KVSTG (2 * KVARR)        // 34816 per stage (Kh, Vh)
#define SMEM_ATTN (2 * QSZ + 2 * KVSTG)   // 104448

__device__ __forceinline__ void load_kv(uint32_t sb,
        const __half* __restrict__ Khp, const __half* __restrict__ Vhp,
        int kv0, int tid) {
#pragma unroll
    for (int tpass = 0; tpass < 8; tpass++) {
        int idx = tid + tpass * 128;        // 0..1023
        int r = idx >> 4, cc = idx & 15;
        uint32_t so = (uint32_t)r * ARSB + (uint32_t)cc * 16u;
        size_t go = (size_t)(kv0 + r) * HD + cc * 8;
        cp16(sb +         so, Khp + go);
        cp16(sb + KVARR + so, Vhp + go);
    }
}

__global__ void __launch_bounds__(128) attn_mma() {
    extern __shared__ __align__(128) char asmem[];
    const uint32_t s0  = smem_u32(asmem);
    const uint32_t qhS = s0;
    const uint32_t qlS = s0 + QSZ;
    const uint32_t kvb = s0 + 2 * QSZ;

    const int i0 = gridDim.x - 1 - blockIdx.x;    // heavy blocks first
    const int bh = blockIdx.y;                    // b*16 + h
    const int b  = bh >> 4;
    const int h  = bh & 15;
    const int hkv = h & 7;

    const __half* Qhp = g_Qh + (size_t)bh * TT * HD;
    const __half* Qlp = g_Ql + (size_t)bh * TT * HD;
    const size_t kvo = ((size_t)b * NH_KV + hkv) * TT * HD;
    const __half* Khp = g_Kh + kvo;
    const __half* Vhp = g_Vh + kvo;

    const int tid = threadIdx.x, lid = tid & 31, wid = tid >> 5;
    const int t4 = lid >> 2, t2g = lid & 3;
    const int warpRow = wid * 16;

    const uint32_t a_off = (uint32_t)(warpRow + (lid & 7) + ((lid >> 3) & 1) * 8) * ARSB +
                           (uint32_t)(lid >> 4) * 16u;
    const uint32_t bk_off = (uint32_t)(lid & 7) * ARSB + (uint32_t)(lid >> 3) * 16u;
    const uint32_t v_off  = (uint32_t)((lid & 7) + ((lid >> 3) & 1) * 8) * ARSB +
                            (uint32_t)(lid >> 4) * 16u;

    // load Q tile (hi+lo): 64 rows x 16 chunks
    {
        int r0q = i0 * 64;
#pragma unroll
        for (int tp = 0; tp < 8; tp++) {
            int idx = tid + tp * 128;       // 0..1023
            int r = idx >> 4, cc = idx & 15;
            uint32_t so = (uint32_t)r * ARSB + (uint32_t)cc * 16u;
            size_t go = (size_t)(r0q + r) * HD + cc * 8;
            cp16(qhS + so, Qhp + go);
            cp16(qlS + so, Qlp + go);
        }
    }
    load_kv(kvb, Khp, Vhp, 0, tid);
    cp_commit();

    float oacc[16][4];
#pragma unroll
    for (int i = 0; i < 16; i++)
#pragma unroll
        for (int j = 0; j < 4; j++) oacc[i][j] = 0.f;
    float mA = -1e30f, mB = -1e30f, lA = 0.f, lB = 0.f;

    const int rowA = i0 * 64 + warpRow + t4;
    const int rowB = rowA + 8;
    const int nj = i0 + 1;

    for (int j = 0; j < nj; j++) {
        if (j + 1 < nj) {
            load_kv(kvb + ((j + 1) & 1) * KVSTG, Khp, Vhp, (j + 1) * 64, tid);
            cp_commit();
            cp_wait<1>();
        } else {
            cp_wait<0>();
        }
        __syncthreads();

        const uint32_t sb = kvb + (j & 1) * KVSTG;

        // ---- S = Q K^T (Q 2-term, K single) ----
        float sa[8][4];
#pragma unroll
        for (int nt = 0; nt < 8; nt++)
#pragma unroll
            for (int q = 0; q < 4; q++) sa[nt][q] = 0.f;

#pragma unroll
        for (int kp = 0; kp < 4; kp++) {
            uint32_t q0h[4], q1h[4], q0l[4], q1l[4];
            ldsm4(q0h, qhS + a_off + kp * 64);
            ldsm4(q1h, qhS + a_off + kp * 64 + 32);
            ldsm4(q0l, qlS + a_off + kp * 64);
            ldsm4(q1l, qlS + a_off + kp * 64 + 32);
#pragma unroll
            for (int nt = 0; nt < 8; nt++) {
                uint32_t kh[4];
                ldsm4(kh, sb + bk_off + nt * (8 * ARSB) + kp * 64);
                mma16816h(sa[nt], q0h, kh);
                mma16816h(sa[nt], q0l, kh);
                mma16816h(sa[nt], q1h, kh + 2);
                mma16816h(sa[nt], q1l, kh + 2);
            }
        }

        // ---- softcap + mask + online softmax ----
        float mxA = -1e30f, mxB = -1e30f;
#pragma unroll
        for (int nt = 0; nt < 8; nt++) {
            int c0 = j * 64 + nt * 8 + 2 * t2g;
            float v0 = softcap(sa[nt][0]);
            float v1 = softcap(sa[nt][1]);
            float v2 = softcap(sa[nt][2]);
            float v3 = softcap(sa[nt][3]);
            if (c0     > rowA) v0 = -1e30f;
            if (c0 + 1 > rowA) v1 = -1e30f;
            if (c0     > rowB) v2 = -1e30f;
            if (c0 + 1 > rowB) v3 = -1e30f;
            sa[nt][0] = v0; sa[nt][1] = v1; sa[nt][2] = v2; sa[nt][3] = v3;
            mxA = fmaxf(mxA, fmaxf(v0, v1));
            mxB = fmaxf(mxB, fmaxf(v2, v3));
        }
        mxA = fmaxf(mxA, __shfl_xor_sync(0xffffffffu, mxA, 1));
        mxA = fmaxf(mxA, __shfl_xor_sync(0xffffffffu, mxA, 2));
        mxB = fmaxf(mxB, __shfl_xor_sync(0xffffffffu, mxB, 1));
        mxB = fmaxf(mxB, __shfl_xor_sync(0xffffffffu, mxB, 2));

        float mAn = fmaxf(mA, mxA), mBn = fmaxf(mB, mxB);
        float fA = __expf(mA - mAn), fB = __expf(mB - mBn);
        mA = mAn; mB = mBn;

        float sA = 0.f, sB = 0.f;
#pragma unroll
        for (int nt = 0; nt < 8; nt++) {
            float p0 = __expf(sa[nt][0] - mA);
            float p1 = __expf(sa[nt][1] - mA);
            float p2 = __expf(sa[nt][2] - mB);
            float p3 = __expf(sa[nt][3] - mB);
            sa[nt][0] = p0; sa[nt][1] = p1; sa[nt][2] = p2; sa[nt][3] = p3;
            sA += p0 + p1; sB += p2 + p3;
        }
        sA += __shfl_xor_sync(0xffffffffu, sA, 1);
        sA += __shfl_xor_sync(0xffffffffu, sA, 2);
        sB += __shfl_xor_sync(0xffffffffu, sB, 1);
        sB += __shfl_xor_sync(0xffffffffu, sB, 2);
        lA = lA * fA + sA;
        lB = lB * fB + sB;
#pragma unroll
        for (int nt = 0; nt < 16; nt++) {
            oacc[nt][0] *= fA; oacc[nt][1] *= fA;
            oacc[nt][2] *= fB; oacc[nt][3] *= fB;
        }

        // ---- O += P V (P single fp16 from registers, V single) ----
#pragma unroll
        for (int ks = 0; ks < 4; ks++) {
            uint32_t pah[4];
            pah[0] = pack2h(sa[2 * ks][0],     sa[2 * ks][1]);
            pah[1] = pack2h(sa[2 * ks][2],     sa[2 * ks][3]);
            pah[2] = pack2h(sa[2 * ks + 1][0], sa[2 * ks + 1][1]);
            pah[3] = pack2h(sa[2 * ks + 1][2], sa[2 * ks + 1][3]);
#pragma unroll
            for (int ntp = 0; ntp < 8; ntp++) {
                uint32_t vh[4];
                ldsm4t(vh, sb + KVARR + v_off + ks * (16 * ARSB) + ntp * 32);
                mma16816h(oacc[2 * ntp],     pah, vh);
                mma16816h(oacc[2 * ntp + 1], pah, vh + 2);
            }
        }
        __syncthreads();
    }

    // ---- epilogue: normalize, write g_Oh (fp16 single) [m][h*128+d] ----
    float invA = 1.f / lA, invB = 1.f / lB;
    size_t mAr = (size_t)b * 2048 + (size_t)rowA;   // rowA is global t
    size_t mBr = mAr + 8;
    int colbase = h * 128 + 2 * t2g;
#pragma unroll
    for (int nt = 0; nt < 16; nt++) {
        int c = colbase + nt * 8;
        *(uint32_t*)(g_Oh + mAr * 2048 + c) =
            pack2h(oacc[nt][0] * invA, oacc[nt][1] * invA);
        *(uint32_t*)(g_Oh + mBr * 2048 + c) =
            pack2h(oacc[nt][2] * invB, oacc[nt][3] * invB);
    }
}

// =====================================================================
// host entry
// =====================================================================
extern "C" void kernel_launch(void* const* d_in, const int* in_sizes, int n_in,
                              void* d_out, int out_size) {
    const float* x  = (const float*)d_in[0];
    // d_in[1] = mask (deterministic causal tril -> ignored)
    const float* qk = (const float*)d_in[2];
    const float* kk = (const float*)d_in[3];
    const float* vk = (const float*)d_in[4];
    const float* ok = (const float*)d_in[5];
    float* out = (float*)d_out;

    cudaFuncSetAttribute(gemm_f16<0>, cudaFuncAttributeMaxDynamicSharedMemorySize, SMEM_GEMM);
    cudaFuncSetAttribute(gemm_f16<1>, cudaFuncAttributeMaxDynamicSharedMemorySize, SMEM_GEMM);
    cudaFuncSetAttribute(attn_mma, cudaFuncAttributeMaxDynamicSharedMemorySize, SMEM_ATTN);

    // rope table + input conversion
    rope_tab<<<512, 256>>>();
    cvt_x<<<8192, 256>>>(x);
    cvt_w_all<<<dim3(192, 64), 256>>>(qk, kk, vk, ok);

    // fused QKV projection + rope epilogue (CTA 128x128, warp 64x32, BK=64)
    gemm_f16<0><<<dim3(32, 32), 256, SMEM_GEMM>>>(nullptr);

    // tensor-core flash attention (writes g_Oh fp16 single)
    attn_mma<<<dim3(TT / 64, TB * NH_Q), 128, SMEM_ATTN>>>();

    // output projection
    gemm_f16<1><<<dim3(16, 32), 256, SMEM_GEMM>>>(out);
}